// round 2
// baseline (speedup 1.0000x reference)
#include <cuda_runtime.h>
#include <math.h>

#define BB 64
#define HHH 14
#define WWID 14
#define CC 32
#define OO 10
#define NN (HHH*WWID*CC)      /* 6272 */
#define SPATIAL (HHH*WWID)    /* 196  */
#define CHUNKS 7
#define S_PER_BLOCK (SPATIAL/CHUNKS)  /* 28 */
#define EPSV 1e-9f

// Deterministic per-chunk partial sums: [chunk][b][o][33] = (T1[16], T2[16], S0)
__device__ float g_part[CHUNKS*BB*OO*33];
// Per-(b,o) coefficients for next iteration: A2[16], C0, MU[16]
__device__ float g_coef[BB*OO*33];

template<int IT>
__global__ __launch_bounds__(320)
void stats_kernel(const float* __restrict__ pose,
                  const float* __restrict__ act,
                  const float* __restrict__ wmat)
{
    __shared__ float pose_s[CC*20];   // 32 points x 16 floats, padded stride 20
    __shared__ float act_s[CC];
    __shared__ float logit_s[OO*33];

    const int c   = threadIdx.x;      // input-capsule channel (lane)
    const int o   = threadIdx.y;      // output capsule (warp)
    const int tid = o*32 + c;
    const int b   = blockIdx.y;
    const int s0  = blockIdx.x * S_PER_BLOCK;

    // w[c][o][j*4+k] lives in registers for the whole block
    float wr[16];
#pragma unroll
    for (int jk = 0; jk < 16; jk++) wr[jk] = wmat[(c*OO + o)*16 + jk];

    float A2[16], MU[16], C0f = 0.f;
    if (IT > 0) {
        const float* cf = &g_coef[(b*OO + o)*33];
#pragma unroll
        for (int d = 0; d < 16; d++) A2[d] = cf[d];
        C0f = cf[16];
#pragma unroll
        for (int d = 0; d < 16; d++) MU[d] = cf[17+d];
    }

    float S0 = 0.f, S1[16], S2[16];
#pragma unroll
    for (int d = 0; d < 16; d++) { S1[d] = 0.f; S2[d] = 0.f; }

    for (int ss = 0; ss < S_PER_BLOCK; ss++) {
        const int s = s0 + ss;

        // Cooperative stage of 32 points x 16 floats of pose (+32 activations)
        const float* pg = pose + ((size_t)b*NN + (size_t)s*CC)*16;
        if (tid < 128) {
            float4 v4 = ((const float4*)pg)[tid];
            *(float4*)&pose_s[(tid>>2)*20 + (tid&3)*4] = v4;
        } else if (tid < 160) {
            act_s[tid-128] = act[(size_t)b*NN + (size_t)s*CC + (tid-128)];
        }
        __syncthreads();

        // votes v[i*4+k] = sum_j pose[i][j] * w[j*4+k]
        float v[16];
#pragma unroll
        for (int i = 0; i < 4; i++) {
            float4 p4 = *(const float4*)&pose_s[c*20 + i*4];
#pragma unroll
            for (int k = 0; k < 4; k++) {
                float a = p4.x * wr[k];
                a = fmaf(p4.y, wr[4 +k], a);
                a = fmaf(p4.z, wr[8 +k], a);
                a = fmaf(p4.w, wr[12+k], a);
                v[i*4+k] = a;
            }
        }
        // coordinate addition (d=3: w-offset, d=7: h-offset)
        v[3] += ((s % WWID) + 0.5f) * (1.0f/WWID);
        v[7] += ((s / WWID) + 0.5f) * (1.0f/HHH);

        // Centered votes u = v - mu_prev (mu_prev = 0 for IT==0)
        float u[16], u2[16];
        if (IT == 0) {
#pragma unroll
            for (int d = 0; d < 16; d++) { u[d] = v[d]; u2[d] = v[d]*v[d]; }
        } else {
#pragma unroll
            for (int d = 0; d < 16; d++) { u[d] = v[d] - MU[d]; u2[d] = u[d]*u[d]; }
        }

        float rr;
        if (IT == 0) {
            rr = 1.0f/OO;
        } else {
            // logit = C0 + sum_d u^2 * (-0.5/var)   (== log(act_out+eps)+ln_p)
            float lg = C0f;
#pragma unroll
            for (int d = 0; d < 16; d++) lg = fmaf(u2[d], A2[d], lg);
            logit_s[o*33 + c] = lg;
            __syncthreads();
            float lv[OO];
            float m = -1e30f;
#pragma unroll
            for (int oo = 0; oo < OO; oo++) {
                lv[oo] = logit_s[oo*33 + c];
                m = fmaxf(m, lv[oo]);
            }
            float ssum = 0.f;
#pragma unroll
            for (int oo = 0; oo < OO; oo++) ssum += __expf(lv[oo]-m);
            rr = __expf(lg - m) / ssum;
        }

        const float rp = rr * act_s[c];
        S0 += rp;
#pragma unroll
        for (int d = 0; d < 16; d++) {
            S1[d] = fmaf(rp, u[d],  S1[d]);
            S2[d] = fmaf(rp, u2[d], S2[d]);
        }
        __syncthreads();  // protect pose_s/act_s/logit_s before next stage
    }

    // warp reduction over the 32 c-lanes (warp == fixed o)
#pragma unroll
    for (int off = 16; off > 0; off >>= 1) {
        S0 += __shfl_down_sync(0xffffffffu, S0, off);
#pragma unroll
        for (int d = 0; d < 16; d++) {
            S1[d] += __shfl_down_sync(0xffffffffu, S1[d], off);
            S2[d] += __shfl_down_sync(0xffffffffu, S2[d], off);
        }
    }
    if (c == 0) {
        float* gp = &g_part[(((size_t)blockIdx.x*BB + b)*OO + o)*33];
#pragma unroll
        for (int d = 0; d < 16; d++) { gp[d] = S1[d]; gp[16+d] = S2[d]; }
        gp[32] = S0;
    }
}

__global__ void finalize_kernel(int it,
                                const float* __restrict__ beta_a,
                                const float* __restrict__ beta_u,
                                float* __restrict__ out)
{
    const int b   = blockIdx.x;
    const int tid = threadIdx.x;        // 0..159
    const int o   = tid >> 4;
    const int d   = tid & 15;

    float T1 = 0.f, T2 = 0.f, S0 = 0.f;
#pragma unroll
    for (int ch = 0; ch < CHUNKS; ch++) {
        const float* gp = &g_part[(((size_t)ch*BB + b)*OO + o)*33];
        T1 += gp[d];
        T2 += gp[16+d];
        S0 += gp[32];
    }

    const float mu_prev = (it == 0) ? 0.f : g_coef[(b*OO + o)*33 + 17 + d];

    // Exact shifted-moment identity evaluated in fp64:
    //   S1 = T1 + mu_prev*S0;  mu = S1/rs;  e = mu - mu_prev
    //   sum rp*(v-mu)^2 = T2 - 2*e*T1 + e^2*S0   (exact for any shift)
    const double S0d = (double)S0;
    const double rsd = S0d + (double)EPSV;
    const double S1d = (double)T1 + (double)mu_prev * S0d;
    const double mud = S1d / rsd;
    const double e   = mud - (double)mu_prev;
    double varnum = (double)T2 - 2.0*e*(double)T1 + e*e*S0d;
    if (varnum < 0.0) varnum = 0.0;
    const double vard = varnum / rsd + (double)EPSV;

    const float mu   = (float)mud;
    const float var  = (float)vard;
    const float lvar = logf(var);
    const float iv   = 1.0f/var;
    const float rs   = (float)rsd;

    // reduce lvar across the 16 d-lanes
    float r1 = lvar;
#pragma unroll
    for (int m = 8; m > 0; m >>= 1)
        r1 += __shfl_xor_sync(0xffffffffu, r1, m);

    const float cost     = rs * (16.0f*beta_u[o] + 0.5f*r1);
    const float inv_temp = 1.0f + (float)it;   // 1, 2, 3
    const float z        = inv_temp * (beta_a[o] - cost);
    const float actv     = 1.0f / (1.0f + expf(-z));

    if (it < 2) {
        // next-iter logit(v) = C0 + sum_d (v-mu)^2 * (-0.5/var)
        float* cf = &g_coef[(b*OO + o)*33];
        cf[d]    = -0.5f*iv;
        cf[17+d] = mu;
        if (d == 0)
            cf[16] = logf(actv + EPSV)
                   - 0.5f*(16.0f*1.8378770664093453f /*ln(2*pi)*/ + r1);
    } else {
        out[(b*OO + o)*16 + d] = mu;                 // pose_out (B,O,16)
        if (d == 0) out[BB*OO*16 + b*OO + o] = actv; // activation_out (B,O)
    }
}

extern "C" void kernel_launch(void* const* d_in, const int* in_sizes, int n_in,
                              void* d_out, int out_size)
{
    const float* pose = (const float*)d_in[0];  // (B,H,W,C,16)
    const float* actv = (const float*)d_in[1];  // (B,H,W,C,1)
    const float* wmat = (const float*)d_in[2];  // (C,O,4,4)
    const float* ba   = (const float*)d_in[3];  // (1,1,O,1)
    const float* bu   = (const float*)d_in[4];  // (1,1,O,1)
    float* out = (float*)d_out;                 // pose(B,O,16) then act(B,O)

    dim3 blk(32, 10);
    dim3 grd(CHUNKS, BB);

    stats_kernel<0><<<grd, blk>>>(pose, actv, wmat);
    finalize_kernel<<<BB, 160>>>(0, ba, bu, out);
    stats_kernel<1><<<grd, blk>>>(pose, actv, wmat);
    finalize_kernel<<<BB, 160>>>(1, ba, bu, out);
    stats_kernel<2><<<grd, blk>>>(pose, actv, wmat);
    finalize_kernel<<<BB, 160>>>(2, ba, bu, out);
}

// round 3
// speedup vs baseline: 1.0984x; 1.0984x over previous
#include <cuda_runtime.h>
#include <math.h>

#define BB 64
#define HH 14
#define WW 14
#define CC 32
#define OO 10
#define NN (HH*WW*CC)          /* 6272 */
#define SPATIAL (HH*WW)        /* 196  */
#define HALF_S (SPATIAL/2)     /* 98   */
#define NBLK (BB*2)            /* 128 blocks, all co-resident on 148 SMs */
#define EPSV 1e-9f
#define LOG2E 1.4426950408889634f
#define LN2PI 1.8378770664093453f

// cross-block partials: [half][b][o][33] = (S1[16], S2[16], S0)
__device__ float g_part[2*BB*OO*33];
__device__ unsigned int g_ctr;
__device__ unsigned int g_epoch;

typedef unsigned long long u64;
__device__ __forceinline__ u64 pk2(float lo, float hi){ u64 r; asm("mov.b64 %0,{%1,%2};" :"=l"(r):"f"(lo),"f"(hi)); return r; }
__device__ __forceinline__ void upk2(u64 a, float& lo, float& hi){ asm("mov.b64 {%0,%1},%2;":"=f"(lo),"=f"(hi):"l"(a)); }
__device__ __forceinline__ u64 fma2(u64 a,u64 b,u64 c){ u64 r; asm("fma.rn.f32x2 %0,%1,%2,%3;":"=l"(r):"l"(a),"l"(b),"l"(c)); return r; }
__device__ __forceinline__ u64 add2(u64 a,u64 b){ u64 r; asm("add.rn.f32x2 %0,%1,%2;":"=l"(r):"l"(a),"l"(b)); return r; }
__device__ __forceinline__ u64 mul2(u64 a,u64 b){ u64 r; asm("mul.rn.f32x2 %0,%1,%2;":"=l"(r):"l"(a),"l"(b)); return r; }
__device__ __forceinline__ float ex2f(float x){ float r; asm("ex2.approx.f32 %0,%1;":"=f"(r):"f"(x)); return r; }
__device__ __forceinline__ float rcpf(float x){ float r; asm("rcp.approx.f32 %0,%1;":"=f"(r):"f"(x)); return r; }

// all threads call; fences own writes, then block arrives; epoch-based release
__device__ __forceinline__ void grid_barrier(unsigned target_epoch){
    __threadfence();
    __syncthreads();
    if (threadIdx.x == 0 && threadIdx.y == 0){
        unsigned a = atomicAdd(&g_ctr, 1u);
        if (a == NBLK-1u){
            atomicExch(&g_ctr, 0u);
            __threadfence();
            atomicAdd(&g_epoch, 1u);
        } else {
            while ((int)(*(volatile unsigned*)&g_epoch) - (int)target_epoch < 0) { }
        }
    }
    __syncthreads();
}

template<int IT>
__device__ __forceinline__ void stats_pass(
    const float* __restrict__ pose_blk,   // pose + (b*NN + s0*CC)*16
    const float* __restrict__ act_s,
    const float2* __restrict__ offs_s,
    float* lg_s, float* ex_s,
    const float* coefA, const float* coefM, const float* coefC,
    const u64 wpk[4][4],
    int c, int o, float* gp /* &g_part[(half*BB+b)*OO*33 + o*33] */)
{
    u64 A2[2][4], nMU[2][4]; float C0 = 0.f;
    if (IT > 0){
        C0 = coefC[o];
#pragma unroll
        for (int p = 0; p < 2; p++)
#pragma unroll
        for (int k = 0; k < 4; k++){
            A2[p][k]  = pk2( coefA[o*16 + p*8 + k],  coefA[o*16 + p*8 + 4 + k]);
            nMU[p][k] = pk2(-coefM[o*16 + p*8 + k], -coefM[o*16 + p*8 + 4 + k]);
        }
    }

    u64 S1[2][4], S2[2][4]; float S0 = 0.f;
#pragma unroll
    for (int p = 0; p < 2; p++)
#pragma unroll
    for (int k = 0; k < 4; k++){ S1[p][k] = 0ull; S2[p][k] = 0ull; }

    for (int ss = 0; ss < HALF_S; ss++){
        const float4* pr = (const float4*)(pose_blk + ((size_t)ss*CC + c)*16);
        float4 pa = pr[0], pb = pr[1], pc4 = pr[2], pd = pr[3];

        // pp[p][j] = {pose[8p+j], pose[8p+4+j]}  (lo=i=2p, hi=i=2p+1)
        u64 pp[2][4];
        pp[0][0] = pk2(pa.x, pb.x); pp[0][1] = pk2(pa.y, pb.y);
        pp[0][2] = pk2(pa.z, pb.z); pp[0][3] = pk2(pa.w, pb.w);
        pp[1][0] = pk2(pc4.x, pd.x); pp[1][1] = pk2(pc4.y, pd.y);
        pp[1][2] = pk2(pc4.z, pd.z); pp[1][3] = pk2(pc4.w, pd.w);

        // votes: v[p][k] = {v[d=p*8+k], v[d=p*8+4+k]}
        u64 v[2][4];
#pragma unroll
        for (int p = 0; p < 2; p++)
#pragma unroll
        for (int k = 0; k < 4; k++){
            u64 acc = mul2(pp[p][0], wpk[0][k]);
            acc = fma2(pp[p][1], wpk[1][k], acc);
            acc = fma2(pp[p][2], wpk[2][k], acc);
            acc = fma2(pp[p][3], wpk[3][k], acc);
            v[p][k] = acc;
        }
        // coord addition: d=3 -> v[0][3].lo, d=7 -> v[0][3].hi
        float2 of = offs_s[ss];
        v[0][3] = add2(v[0][3], pk2(of.x, of.y));

        u64 u[2][4], u2[2][4];
#pragma unroll
        for (int p = 0; p < 2; p++)
#pragma unroll
        for (int k = 0; k < 4; k++){
            u[p][k]  = (IT > 0) ? add2(v[p][k], nMU[p][k]) : v[p][k];
            u2[p][k] = mul2(u[p][k], u[p][k]);
        }

        float rr;
        if (IT == 0){
            rr = 0.1f;
        } else {
            // logit (log2-domain, A2/C0 pre-scaled by log2e)
            u64 lgp = mul2(u2[0][0], A2[0][0]);
            lgp = fma2(u2[0][1], A2[0][1], lgp);
            lgp = fma2(u2[0][2], A2[0][2], lgp);
            lgp = fma2(u2[0][3], A2[0][3], lgp);
            lgp = fma2(u2[1][0], A2[1][0], lgp);
            lgp = fma2(u2[1][1], A2[1][1], lgp);
            lgp = fma2(u2[1][2], A2[1][2], lgp);
            lgp = fma2(u2[1][3], A2[1][3], lgp);
            float l0, l1; upk2(lgp, l0, l1);
            float lg = C0 + (l0 + l1);
            lg_s[o*33 + c] = lg;
            __syncthreads();
            float m = lg_s[c];
#pragma unroll
            for (int oo = 1; oo < OO; oo++) m = fmaxf(m, lg_s[oo*33 + c]);
            float ex = ex2f(lg - m);
            ex_s[o*33 + c] = ex;
            __syncthreads();
            float ssum = ex_s[c];
#pragma unroll
            for (int oo = 1; oo < OO; oo++) ssum += ex_s[oo*33 + c];
            rr = ex * rcpf(ssum);
        }

        const float rp  = rr * act_s[ss*CC + c];
        const u64  rpk  = pk2(rp, rp);
        S0 += rp;
#pragma unroll
        for (int p = 0; p < 2; p++)
#pragma unroll
        for (int k = 0; k < 4; k++){
            S1[p][k] = fma2(rpk, u[p][k],  S1[p][k]);
            S2[p][k] = fma2(rpk, u2[p][k], S2[p][k]);
        }
    }

    // unpack to true-d order, warp-reduce over c, lane0 writes partials
    float f[33];
#pragma unroll
    for (int p = 0; p < 2; p++)
#pragma unroll
    for (int k = 0; k < 4; k++){
        upk2(S1[p][k], f[p*8+k],      f[p*8+4+k]);
        upk2(S2[p][k], f[16+p*8+k],   f[16+p*8+4+k]);
    }
    f[32] = S0;
#pragma unroll
    for (int off = 16; off > 0; off >>= 1){
#pragma unroll
        for (int i = 0; i < 33; i++)
            f[i] += __shfl_down_sync(0xffffffffu, f[i], off);
    }
    if (c == 0){
#pragma unroll
        for (int i = 0; i < 33; i++) gp[i] = f[i];
    }
}

__device__ __forceinline__ void block_finalize(
    int it, int b, int tid,
    const float* __restrict__ beta_a, const float* __restrict__ beta_u,
    float* coefA, float* coefM, float* coefC, float* out)
{
    if (tid < 160){
        const int o = tid >> 4, d = tid & 15;
        const float* gp0 = &g_part[((0*BB + b)*OO + o)*33];
        const float* gp1 = &g_part[((1*BB + b)*OO + o)*33];
        const float T1 = __ldcg(gp0 + d)      + __ldcg(gp1 + d);
        const float T2 = __ldcg(gp0 + 16 + d) + __ldcg(gp1 + 16 + d);
        const float S0 = __ldcg(gp0 + 32)     + __ldcg(gp1 + 32);
        const float mu_prev = (it == 0) ? 0.f : coefM[o*16 + d];

        // exact shifted-moment identity in fp64 (cancellation-safe)
        const double S0d = (double)S0;
        const double rsd = S0d + (double)EPSV;
        const double S1d = (double)T1 + (double)mu_prev * S0d;
        const double mud = S1d / rsd;
        const double e   = mud - (double)mu_prev;
        double varnum = (double)T2 - 2.0*e*(double)T1 + e*e*S0d;
        if (varnum < 0.0) varnum = 0.0;
        const double vard = varnum / rsd + (double)EPSV;

        const float mu   = (float)mud;
        const float var  = (float)vard;
        const float lvar = logf(var);
        const float iv   = 1.0f/var;
        const float rs   = (float)rsd;

        float r1 = lvar;
#pragma unroll
        for (int m = 8; m > 0; m >>= 1)
            r1 += __shfl_xor_sync(0xffffffffu, r1, m);

        const float cost     = rs * (16.0f*beta_u[o] + 0.5f*r1);
        const float inv_temp = 1.0f + (float)it;
        const float z        = inv_temp * (beta_a[o] - cost);
        const float actv     = 1.0f / (1.0f + expf(-z));

        if (it < 2){
            coefA[o*16 + d] = -0.5f*iv*LOG2E;
            coefM[o*16 + d] = mu;
            if (d == 0)
                coefC[o] = (logf(actv + EPSV) - 0.5f*(16.0f*LN2PI + r1)) * LOG2E;
        } else {
            out[(b*OO + o)*16 + d] = mu;
            if (d == 0) out[BB*OO*16 + b*OO + o] = actv;
        }
    }
    __syncthreads();
}

__global__ __launch_bounds__(320)
void fccaps_kernel(const float* __restrict__ pose,
                   const float* __restrict__ act,
                   const float* __restrict__ wmat,
                   const float* __restrict__ beta_a,
                   const float* __restrict__ beta_u,
                   float* __restrict__ out)
{
    __shared__ float  act_s[HALF_S*CC];
    __shared__ float2 offs_s[HALF_S];
    __shared__ float  lg_s[OO*33];
    __shared__ float  ex_s[OO*33];
    __shared__ float  coefA[OO*16];
    __shared__ float  coefM[OO*16];
    __shared__ float  coefC[OO];
    __shared__ unsigned e0_s;

    const int c   = threadIdx.x;
    const int o   = threadIdx.y;
    const int tid = o*32 + c;
    const int b    = blockIdx.x >> 1;
    const int half = blockIdx.x & 1;
    const int s0   = half * HALF_S;

    // stage activations + coord offsets once
    for (int i = tid; i < HALF_S*CC; i += 320)
        act_s[i] = act[(size_t)b*NN + (size_t)s0*CC + i];
    if (tid < HALF_S){
        const int s = s0 + tid;
        offs_s[tid] = make_float2(((s % WW) + 0.5f)*(1.0f/WW),
                                  ((s / WW) + 0.5f)*(1.0f/HH));
    }
    if (tid == 0) e0_s = *(volatile unsigned*)&g_epoch;

    // weights, replicated-packed, resident for whole kernel
    u64 wpk[4][4];
#pragma unroll
    for (int j = 0; j < 4; j++)
#pragma unroll
    for (int k = 0; k < 4; k++){
        const float wv = wmat[((size_t)(c*OO + o))*16 + j*4 + k];
        wpk[j][k] = pk2(wv, wv);
    }
    __syncthreads();
    const unsigned e0 = e0_s;

    const float* pose_blk = pose + ((size_t)b*NN + (size_t)s0*CC)*16;
    float* gp = &g_part[(((size_t)half*BB + b)*OO + o)*33];

    stats_pass<0>(pose_blk, act_s, offs_s, lg_s, ex_s, coefA, coefM, coefC, wpk, c, o, gp);
    grid_barrier(e0 + 1);
    block_finalize(0, b, tid, beta_a, beta_u, coefA, coefM, coefC, out);

    stats_pass<1>(pose_blk, act_s, offs_s, lg_s, ex_s, coefA, coefM, coefC, wpk, c, o, gp);
    grid_barrier(e0 + 2);
    block_finalize(1, b, tid, beta_a, beta_u, coefA, coefM, coefC, out);

    stats_pass<2>(pose_blk, act_s, offs_s, lg_s, ex_s, coefA, coefM, coefC, wpk, c, o, gp);
    grid_barrier(e0 + 3);
    if (half == 0)
        block_finalize(2, b, tid, beta_a, beta_u, coefA, coefM, coefC, out);
}

extern "C" void kernel_launch(void* const* d_in, const int* in_sizes, int n_in,
                              void* d_out, int out_size)
{
    const float* pose = (const float*)d_in[0];  // (B,H,W,C,16)
    const float* actv = (const float*)d_in[1];  // (B,H,W,C,1)
    const float* wmat = (const float*)d_in[2];  // (C,O,4,4)
    const float* ba   = (const float*)d_in[3];  // (1,1,O,1)
    const float* bu   = (const float*)d_in[4];  // (1,1,O,1)
    float* out = (float*)d_out;                 // pose(B,O,16) then act(B,O)

    dim3 blk(32, 10);
    fccaps_kernel<<<NBLK, blk>>>(pose, actv, wmat, ba, bu, out);
}

// round 4
// speedup vs baseline: 1.1506x; 1.0475x over previous
#include <cuda_runtime.h>
#include <math.h>

#define BB 64
#define HH 14
#define WW 14
#define CC 32
#define OO 10
#define NN (HH*WW*CC)          /* 6272 */
#define SPATIAL (HH*WW)        /* 196  */
#define HALF_S (SPATIAL/2)     /* 98   */
#define NBLK (BB*2)            /* 128 persistent blocks */
#define EPSV 1e-9f
#define LOG2E 1.4426950408889634f
#define LN2PI 1.8378770664093453f

// double-buffered cross-block partials: [parity][half][b][o][33] = (S1[16],S2[16],S0)
__device__ float g_part[2][2*BB*OO*33];
__device__ unsigned int g_ctr;
__device__ unsigned int g_epoch;

typedef unsigned long long u64;
__device__ __forceinline__ u64 pk2(float lo, float hi){ u64 r; asm("mov.b64 %0,{%1,%2};" :"=l"(r):"f"(lo),"f"(hi)); return r; }
__device__ __forceinline__ void upk2(u64 a, float& lo, float& hi){ asm("mov.b64 {%0,%1},%2;":"=f"(lo),"=f"(hi):"l"(a)); }
__device__ __forceinline__ u64 fma2(u64 a,u64 b,u64 c){ u64 r; asm("fma.rn.f32x2 %0,%1,%2,%3;":"=l"(r):"l"(a),"l"(b),"l"(c)); return r; }
__device__ __forceinline__ u64 add2(u64 a,u64 b){ u64 r; asm("add.rn.f32x2 %0,%1,%2;":"=l"(r):"l"(a),"l"(b)); return r; }
__device__ __forceinline__ u64 mul2(u64 a,u64 b){ u64 r; asm("mul.rn.f32x2 %0,%1,%2;":"=l"(r):"l"(a),"l"(b)); return r; }
__device__ __forceinline__ float ex2f(float x){ float r; asm("ex2.approx.f32 %0,%1;":"=f"(r):"f"(x)); return r; }
__device__ __forceinline__ float rcpf(float x){ float r; asm("rcp.approx.f32 %0,%1;":"=f"(r):"f"(x)); return r; }

struct Shm {
    float act[HALF_S*CC];      // 12544 B
    u64   offs[HALF_S];        // packed {w_off, h_off} per point
    float lgA[OO*33];
    float lgB[OO*33];
    float exA[OO*33];
    float exB[OO*33];
    u64   A2pk[OO*8];          // [o][p*4+k] = {A2[d=8p+k], A2[d=8p+4+k]} (log2-scaled)
    u64   Mpk [OO*8];          // packed -mu, same layout
    float Mu  [OO*16];         // plain mu (finalize's mu_prev)
    float C0  [OO];            // log2-domain constant
    unsigned e0;
};

__device__ __forceinline__ void grid_barrier(unsigned target_epoch){
    __threadfence();
    __syncthreads();
    if (threadIdx.x == 0 && threadIdx.y == 0){
        unsigned a = atomicAdd(&g_ctr, 1u);
        if (a == NBLK-1u){
            atomicExch(&g_ctr, 0u);
            __threadfence();
            atomicAdd(&g_epoch, 1u);
        } else {
            while ((int)(*(volatile unsigned*)&g_epoch) - (int)target_epoch < 0) { }
        }
    }
    __syncthreads();
}

template<int IT>
__device__ __forceinline__ void stats_pass(
    const float* __restrict__ pose_blk, Shm* sh,
    const u64 wpk[4][4], int c, int o, float* gp)
{
    u64 A2[2][4], nMU[2][4]; float C0 = 0.f;
    if (IT > 0){
        C0 = sh->C0[o];
#pragma unroll
        for (int p = 0; p < 2; p++)
#pragma unroll
        for (int k = 0; k < 4; k++){
            A2[p][k]  = sh->A2pk[o*8 + p*4 + k];
            nMU[p][k] = sh->Mpk [o*8 + p*4 + k];
        }
    }

    u64 S1[2][4], S2[2][4]; float S0 = 0.f;
#pragma unroll
    for (int p = 0; p < 2; p++)
#pragma unroll
    for (int k = 0; k < 4; k++){ S1[p][k] = 0ull; S2[p][k] = 0ull; }

    const float4* pr = (const float4*)pose_blk + (size_t)c*4;
    int aidx = c;
    float* lgAme = sh->lgA + o*33 + c;
    float* lgBme = sh->lgB + o*33 + c;
    float* exAme = sh->exA + o*33 + c;
    float* exBme = sh->exB + o*33 + c;

    for (int ss = 0; ss < HALF_S; ss += 2, pr += 2*CC*4, aidx += 2*CC){
        // ---- load both points' pose (8x LDG.128 in flight) ----
        const float4* pr1 = pr + CC*4;
        float4 a0 = pr [0], b0 = pr [1], c0 = pr [2], d0 = pr [3];
        float4 a1 = pr1[0], b1 = pr1[1], c1 = pr1[2], d1 = pr1[3];

        u64 pp0[2][4], pp1[2][4];
        pp0[0][0]=pk2(a0.x,b0.x); pp0[0][1]=pk2(a0.y,b0.y);
        pp0[0][2]=pk2(a0.z,b0.z); pp0[0][3]=pk2(a0.w,b0.w);
        pp0[1][0]=pk2(c0.x,d0.x); pp0[1][1]=pk2(c0.y,d0.y);
        pp0[1][2]=pk2(c0.z,d0.z); pp0[1][3]=pk2(c0.w,d0.w);
        pp1[0][0]=pk2(a1.x,b1.x); pp1[0][1]=pk2(a1.y,b1.y);
        pp1[0][2]=pk2(a1.z,b1.z); pp1[0][3]=pk2(a1.w,b1.w);
        pp1[1][0]=pk2(c1.x,d1.x); pp1[1][1]=pk2(c1.y,d1.y);
        pp1[1][2]=pk2(c1.z,d1.z); pp1[1][3]=pk2(c1.w,d1.w);

        // ---- u = votes(+coord) - mu_prev, both points ----
        u64 u0[2][4], u1[2][4];
#pragma unroll
        for (int p = 0; p < 2; p++)
#pragma unroll
        for (int k = 0; k < 4; k++){
            u64 acc0, acc1;
            if (IT > 0){ acc0 = fma2(pp0[p][0], wpk[0][k], nMU[p][k]);
                         acc1 = fma2(pp1[p][0], wpk[0][k], nMU[p][k]); }
            else       { acc0 = mul2(pp0[p][0], wpk[0][k]);
                         acc1 = mul2(pp1[p][0], wpk[0][k]); }
            acc0 = fma2(pp0[p][1], wpk[1][k], acc0);
            acc1 = fma2(pp1[p][1], wpk[1][k], acc1);
            acc0 = fma2(pp0[p][2], wpk[2][k], acc0);
            acc1 = fma2(pp1[p][2], wpk[2][k], acc1);
            acc0 = fma2(pp0[p][3], wpk[3][k], acc0);
            acc1 = fma2(pp1[p][3], wpk[3][k], acc1);
            u0[p][k] = acc0; u1[p][k] = acc1;
        }
        u0[0][3] = add2(u0[0][3], sh->offs[ss]);
        u1[0][3] = add2(u1[0][3], sh->offs[ss+1]);

        u64 q0[2][4], q1[2][4];
#pragma unroll
        for (int p = 0; p < 2; p++)
#pragma unroll
        for (int k = 0; k < 4; k++){
            q0[p][k] = mul2(u0[p][k], u0[p][k]);
            q1[p][k] = mul2(u1[p][k], u1[p][k]);
        }

        float rr0, rr1;
        if (IT == 0){
            rr0 = 0.1f; rr1 = 0.1f;
        } else {
            u64 lp0 = mul2(q0[0][0], A2[0][0]);
            u64 lp1 = mul2(q1[0][0], A2[0][0]);
            lp0 = fma2(q0[0][1], A2[0][1], lp0); lp1 = fma2(q1[0][1], A2[0][1], lp1);
            lp0 = fma2(q0[0][2], A2[0][2], lp0); lp1 = fma2(q1[0][2], A2[0][2], lp1);
            lp0 = fma2(q0[0][3], A2[0][3], lp0); lp1 = fma2(q1[0][3], A2[0][3], lp1);
            lp0 = fma2(q0[1][0], A2[1][0], lp0); lp1 = fma2(q1[1][0], A2[1][0], lp1);
            lp0 = fma2(q0[1][1], A2[1][1], lp0); lp1 = fma2(q1[1][1], A2[1][1], lp1);
            lp0 = fma2(q0[1][2], A2[1][2], lp0); lp1 = fma2(q1[1][2], A2[1][2], lp1);
            lp0 = fma2(q0[1][3], A2[1][3], lp0); lp1 = fma2(q1[1][3], A2[1][3], lp1);
            float x0,y0,x1,y1; upk2(lp0,x0,y0); upk2(lp1,x1,y1);
            const float lg0 = C0 + (x0 + y0);
            const float lg1 = C0 + (x1 + y1);
            *lgAme = lg0; *lgBme = lg1;
            __syncthreads();
            float m0 = sh->lgA[c], m1 = sh->lgB[c];
#pragma unroll
            for (int oo = 1; oo < OO; oo++){
                m0 = fmaxf(m0, sh->lgA[oo*33 + c]);
                m1 = fmaxf(m1, sh->lgB[oo*33 + c]);
            }
            const float e0v = ex2f(lg0 - m0);
            const float e1v = ex2f(lg1 - m1);
            *exAme = e0v; *exBme = e1v;
            __syncthreads();
            float s0 = sh->exA[c], s1 = sh->exB[c];
#pragma unroll
            for (int oo = 1; oo < OO; oo++){
                s0 += sh->exA[oo*33 + c];
                s1 += sh->exB[oo*33 + c];
            }
            rr0 = e0v * rcpf(s0);
            rr1 = e1v * rcpf(s1);
        }

        const float rp0 = rr0 * sh->act[aidx];
        const float rp1 = rr1 * sh->act[aidx + CC];
        S0 += rp0; S0 += rp1;
        const u64 rk0 = pk2(rp0, rp0);
        const u64 rk1 = pk2(rp1, rp1);
#pragma unroll
        for (int p = 0; p < 2; p++)
#pragma unroll
        for (int k = 0; k < 4; k++){
            S1[p][k] = fma2(rk0, u0[p][k], S1[p][k]);
            S1[p][k] = fma2(rk1, u1[p][k], S1[p][k]);
            S2[p][k] = fma2(rk0, q0[p][k], S2[p][k]);
            S2[p][k] = fma2(rk1, q1[p][k], S2[p][k]);
        }
    }

    // unpack to true-d order, warp-reduce over c, lane0 writes partials
    float f[33];
#pragma unroll
    for (int p = 0; p < 2; p++)
#pragma unroll
    for (int k = 0; k < 4; k++){
        upk2(S1[p][k], f[p*8+k],    f[p*8+4+k]);
        upk2(S2[p][k], f[16+p*8+k], f[16+p*8+4+k]);
    }
    f[32] = S0;
#pragma unroll
    for (int off = 16; off > 0; off >>= 1){
#pragma unroll
        for (int i = 0; i < 33; i++)
            f[i] += __shfl_down_sync(0xffffffffu, f[i], off);
    }
    if (c == 0){
#pragma unroll
        for (int i = 0; i < 33; i++) gp[i] = f[i];
    }
}

__device__ __forceinline__ void block_finalize(
    int it, int b, int tid, Shm* sh,
    const float* __restrict__ beta_a, const float* __restrict__ beta_u,
    float* __restrict__ out)
{
    if (tid < 160){
        const int o = tid >> 4, d = tid & 15;
        const float* buf = g_part[it & 1];
        const float* gp0 = &buf[((0*BB + b)*OO + o)*33];
        const float* gp1 = &buf[((1*BB + b)*OO + o)*33];
        const float T1 = __ldcg(gp0 + d)      + __ldcg(gp1 + d);
        const float T2 = __ldcg(gp0 + 16 + d) + __ldcg(gp1 + 16 + d);
        const float S0 = __ldcg(gp0 + 32)     + __ldcg(gp1 + 32);
        const float mu_prev = (it == 0) ? 0.f : sh->Mu[o*16 + d];

        // exact shifted-moment identity in fp64 (cancellation-safe)
        const double S0d = (double)S0;
        const double rsd = S0d + (double)EPSV;
        const double S1d = (double)T1 + (double)mu_prev * S0d;
        const double mud = S1d / rsd;
        const double e   = mud - (double)mu_prev;
        double varnum = (double)T2 - 2.0*e*(double)T1 + e*e*S0d;
        if (varnum < 0.0) varnum = 0.0;
        const double vard = varnum / rsd + (double)EPSV;

        const float mu   = (float)mud;
        const float var  = (float)vard;
        const float lvar = logf(var);
        const float iv   = 1.0f/var;
        const float rs   = (float)rsd;

        float r1 = lvar;
#pragma unroll
        for (int m = 8; m > 0; m >>= 1)
            r1 += __shfl_xor_sync(0xffffffffu, r1, m);

        const float cost     = rs * (16.0f*beta_u[o] + 0.5f*r1);
        const float inv_temp = 1.0f + (float)it;
        const float z        = inv_temp * (beta_a[o] - cost);
        const float actv     = 1.0f / (1.0f + expf(-z));

        if (it < 2){
            const int p = d >> 3, hi = (d >> 2) & 1, k = d & 3;
            ((float*)&sh->A2pk[o*8 + p*4 + k])[hi] = -0.5f*iv*LOG2E;
            ((float*)&sh->Mpk [o*8 + p*4 + k])[hi] = -mu;
            sh->Mu[o*16 + d] = mu;
            if (d == 0)
                sh->C0[o] = (logf(actv + EPSV) - 0.5f*(16.0f*LN2PI + r1)) * LOG2E;
        } else {
            out[(b*OO + o)*16 + d] = mu;
            if (d == 0) out[BB*OO*16 + b*OO + o] = actv;
        }
    }
    __syncthreads();
}

__global__ __launch_bounds__(320)
void fccaps_kernel(const float* __restrict__ pose,
                   const float* __restrict__ act,
                   const float* __restrict__ wmat,
                   const float* __restrict__ beta_a,
                   const float* __restrict__ beta_u,
                   float* __restrict__ out)
{
    __shared__ Shm sh;

    const int c   = threadIdx.x;
    const int o   = threadIdx.y;
    const int tid = o*32 + c;
    const int b    = blockIdx.x >> 1;
    const int half = blockIdx.x & 1;
    const int s0   = half * HALF_S;

    for (int i = tid; i < HALF_S*CC; i += 320)
        sh.act[i] = act[(size_t)b*NN + (size_t)s0*CC + i];
    if (tid < HALF_S){
        const int s = s0 + tid;
        sh.offs[tid] = pk2(((s % WW) + 0.5f)*(1.0f/WW),
                           ((s / WW) + 0.5f)*(1.0f/HH));
    }
    if (tid == 0) sh.e0 = *(volatile unsigned*)&g_epoch;

    u64 wpk[4][4];
#pragma unroll
    for (int j = 0; j < 4; j++)
#pragma unroll
    for (int k = 0; k < 4; k++){
        const float wv = wmat[((size_t)(c*OO + o))*16 + j*4 + k];
        wpk[j][k] = pk2(wv, wv);
    }
    __syncthreads();
    const unsigned e0 = sh.e0;

    const float* pose_blk = pose + ((size_t)b*NN + (size_t)s0*CC)*16;
    const size_t gpi = (((size_t)half*BB + b)*OO + o)*33;

    stats_pass<0>(pose_blk, &sh, wpk, c, o, &g_part[0][gpi]);
    grid_barrier(e0 + 1);
    block_finalize(0, b, tid, &sh, beta_a, beta_u, out);

    stats_pass<1>(pose_blk, &sh, wpk, c, o, &g_part[1][gpi]);
    grid_barrier(e0 + 2);
    block_finalize(1, b, tid, &sh, beta_a, beta_u, out);

    stats_pass<2>(pose_blk, &sh, wpk, c, o, &g_part[0][gpi]);
    grid_barrier(e0 + 3);
    if (half == 0)
        block_finalize(2, b, tid, &sh, beta_a, beta_u, out);
}

extern "C" void kernel_launch(void* const* d_in, const int* in_sizes, int n_in,
                              void* d_out, int out_size)
{
    const float* pose = (const float*)d_in[0];  // (B,H,W,C,16)
    const float* actv = (const float*)d_in[1];  // (B,H,W,C,1)
    const float* wmat = (const float*)d_in[2];  // (C,O,4,4)
    const float* ba   = (const float*)d_in[3];  // (1,1,O,1)
    const float* bu   = (const float*)d_in[4];  // (1,1,O,1)
    float* out = (float*)d_out;                 // pose(B,O,16) then act(B,O)

    dim3 blk(32, 10);
    fccaps_kernel<<<NBLK, blk>>>(pose, actv, wmat, ba, bu, out);
}

// round 5
// speedup vs baseline: 1.7285x; 1.5023x over previous
#include <cuda_runtime.h>
#include <math.h>

#define BB 64
#define HH 14
#define WW 14
#define CC 32
#define OO 10
#define NN (HH*WW*CC)          /* 6272 */
#define SPATIAL (HH*WW)        /* 196  */
#define HALF_S 98
#define NBLK 128               /* persistent blocks */
#define G 10                   /* points per staged group */
#define NGRP 10                /* 9 full groups + one of 8 */
#define EPSV 1e-9f
#define LOG2E 1.4426950408889634f
#define LN2PI 1.8378770664093453f

/* double-buffered cross-block partials: [parity][half][b][o][33] */
__device__ float g_part[2][2*BB*OO*33];
__device__ unsigned int g_ctr;
__device__ unsigned int g_epoch;

typedef unsigned long long u64;
__device__ __forceinline__ u64 pk2(float lo, float hi){ u64 r; asm("mov.b64 %0,{%1,%2};" :"=l"(r):"f"(lo),"f"(hi)); return r; }
__device__ __forceinline__ void upk2(u64 a, float& lo, float& hi){ asm("mov.b64 {%0,%1},%2;":"=f"(lo),"=f"(hi):"l"(a)); }
__device__ __forceinline__ u64 fma2(u64 a,u64 b,u64 c){ u64 r; asm("fma.rn.f32x2 %0,%1,%2,%3;":"=l"(r):"l"(a),"l"(b),"l"(c)); return r; }
__device__ __forceinline__ u64 add2(u64 a,u64 b){ u64 r; asm("add.rn.f32x2 %0,%1,%2;":"=l"(r):"l"(a),"l"(b)); return r; }
__device__ __forceinline__ u64 mul2(u64 a,u64 b){ u64 r; asm("mul.rn.f32x2 %0,%1,%2;":"=l"(r):"l"(a),"l"(b)); return r; }
__device__ __forceinline__ float ex2f(float x){ float r; asm("ex2.approx.f32 %0,%1;":"=f"(r):"f"(x)); return r; }
__device__ __forceinline__ float rcpf(float x){ float r; asm("rcp.approx.f32 %0,%1;":"=f"(r):"f"(x)); return r; }

struct Shm {
    float  act [HALF_S*CC];      /* 12544 B */
    float  sbuf[G*CC*18];        /* 23040 B : pair-swizzled pose, stride 18 */
    u64    offs[HALF_S];         /* packed {w_off, h_off} */
    float  lg  [OO*33];          /* logit exchange */
    float2 mrs [CC];             /* {max, rcp(sum)} per c */
    u64    A2pk[OO*8];           /* packed -0.5/var*log2e */
    u64    Mpk [OO*8];           /* packed -mu */
    float  Mu  [OO*16];
    float  C0  [OO];
    unsigned e0;
};

__device__ __forceinline__ void grid_barrier(unsigned target_epoch){
    __threadfence();
    __syncthreads();
    if (threadIdx.x == 0 && threadIdx.y == 0){
        unsigned a = atomicAdd(&g_ctr, 1u);
        if (a == NBLK-1u){
            atomicExch(&g_ctr, 0u);
            __threadfence();
            atomicAdd(&g_epoch, 1u);
        } else {
            while ((int)(*(volatile unsigned*)&g_epoch) - (int)target_epoch < 0) { }
        }
    }
    __syncthreads();
}

template<int IT>
__device__ __forceinline__ void stats_pass(
    const float* __restrict__ pose_blk, Shm* sh,
    const u64 wpk[4][4], int c, int o, float* gp)
{
    u64 A2[2][4], nMU[2][4]; float C0 = 0.f;
    if (IT > 0){
        C0 = sh->C0[o];
#pragma unroll
        for (int p = 0; p < 2; p++)
#pragma unroll
        for (int k = 0; k < 4; k++){
            A2[p][k]  = sh->A2pk[o*8 + p*4 + k];
            nMU[p][k] = sh->Mpk [o*8 + p*4 + k];
        }
    }

    u64 S1[2][4], S2[2][4]; float S0 = 0.f;
#pragma unroll
    for (int p = 0; p < 2; p++)
#pragma unroll
    for (int k = 0; k < 4; k++){ S1[p][k] = 0ull; S2[p][k] = 0ull; }

    const int t = o*32 + c;
    const float4* pb4 = (const float4*)pose_blk;
    float* lgme = sh->lg + o*33 + c;

    /* prologue: prefetch group 0 (320 rows = all threads) */
    float4 pr0, pr1, pr2, pr3;
    {
        const float4* s = pb4 + (size_t)t*4;
        pr0 = s[0]; pr1 = s[1]; pr2 = s[2]; pr3 = s[3];
    }

    for (int g = 0; g < NGRP; g++){
        const int rows = (g == NGRP-1) ? 256 : 320;
        if (t < rows){
            /* pair-swizzle: slot j = {f[j],f[4+j]}, slot 4+j = {f[8+j],f[12+j]} */
            float2* sb2 = (float2*)&sh->sbuf[t*18];
            sb2[0] = make_float2(pr0.x, pr1.x);
            sb2[1] = make_float2(pr0.y, pr1.y);
            sb2[2] = make_float2(pr0.z, pr1.z);
            sb2[3] = make_float2(pr0.w, pr1.w);
            sb2[4] = make_float2(pr2.x, pr3.x);
            sb2[5] = make_float2(pr2.y, pr3.y);
            sb2[6] = make_float2(pr2.z, pr3.z);
            sb2[7] = make_float2(pr2.w, pr3.w);
        }
        __syncthreads();
        if (g < NGRP-1){
            const int nrows = (g == NGRP-2) ? 256 : 320;
            if (t < nrows){
                const float4* s = pb4 + ((size_t)(g+1)*320 + t)*4;
                pr0 = s[0]; pr1 = s[1]; pr2 = s[2]; pr3 = s[3];
            }
        }

        const int pts = (g == NGRP-1) ? 8 : 10;
        const u64* pp8 = (const u64*)(sh->sbuf + c*18);
        const float* ap = sh->act + g*G*CC + c;

        for (int lp = 0; lp < pts; lp++, pp8 += CC*18/2, ap += CC){
            const u64 q0j0 = pp8[0], q0j1 = pp8[1], q0j2 = pp8[2], q0j3 = pp8[3];
            const u64 q1j0 = pp8[4], q1j1 = pp8[5], q1j2 = pp8[6], q1j3 = pp8[7];

            u64 u[2][4];
#pragma unroll
            for (int k = 0; k < 4; k++){
                u64 a0, a1;
                if (IT > 0){ a0 = fma2(q0j0, wpk[0][k], nMU[0][k]);
                             a1 = fma2(q1j0, wpk[0][k], nMU[1][k]); }
                else       { a0 = mul2(q0j0, wpk[0][k]);
                             a1 = mul2(q1j0, wpk[0][k]); }
                a0 = fma2(q0j1, wpk[1][k], a0);
                a1 = fma2(q1j1, wpk[1][k], a1);
                a0 = fma2(q0j2, wpk[2][k], a0);
                a1 = fma2(q1j2, wpk[2][k], a1);
                a0 = fma2(q0j3, wpk[3][k], a0);
                a1 = fma2(q1j3, wpk[3][k], a1);
                u[0][k] = a0; u[1][k] = a1;
            }
            u[0][3] = add2(u[0][3], sh->offs[g*G + lp]);

            u64 q[2][4];
#pragma unroll
            for (int p = 0; p < 2; p++)
#pragma unroll
            for (int k = 0; k < 4; k++)
                q[p][k] = mul2(u[p][k], u[p][k]);

            float rr;
            if (IT == 0){
                rr = 0.1f;
            } else {
                u64 lp2 = mul2(q[0][0], A2[0][0]);
                lp2 = fma2(q[0][1], A2[0][1], lp2);
                lp2 = fma2(q[0][2], A2[0][2], lp2);
                lp2 = fma2(q[0][3], A2[0][3], lp2);
                lp2 = fma2(q[1][0], A2[1][0], lp2);
                lp2 = fma2(q[1][1], A2[1][1], lp2);
                lp2 = fma2(q[1][2], A2[1][2], lp2);
                lp2 = fma2(q[1][3], A2[1][3], lp2);
                float x, y; upk2(lp2, x, y);
                const float lg = C0 + (x + y);
                *lgme = lg;
                __syncthreads();
                if (o == lp){
                    /* rotating reducer: this warp computes max + rcp(sum) per c */
                    float lv[OO];
#pragma unroll
                    for (int oo = 0; oo < OO; oo++) lv[oo] = sh->lg[oo*33 + c];
                    float m = lv[0];
#pragma unroll
                    for (int oo = 1; oo < OO; oo++) m = fmaxf(m, lv[oo]);
                    float sum = 0.f;
#pragma unroll
                    for (int oo = 0; oo < OO; oo++) sum += ex2f(lv[oo] - m);
                    sh->mrs[c] = make_float2(m, rcpf(sum));
                }
                __syncthreads();
                const float2 mr = sh->mrs[c];
                rr = ex2f(lg - mr.x) * mr.y;
            }

            const float rp = rr * (*ap);
            S0 += rp;
            const u64 rk = pk2(rp, rp);
#pragma unroll
            for (int p = 0; p < 2; p++)
#pragma unroll
            for (int k = 0; k < 4; k++){
                S1[p][k] = fma2(rk, u[p][k], S1[p][k]);
                S2[p][k] = fma2(rk, q[p][k], S2[p][k]);
            }
        }
        __syncthreads();   /* all reads of sbuf done before next STS */
    }

    /* unpack to true-d order, warp-reduce over c, lane0 writes partials */
    float f[33];
#pragma unroll
    for (int p = 0; p < 2; p++)
#pragma unroll
    for (int k = 0; k < 4; k++){
        upk2(S1[p][k], f[p*8+k],    f[p*8+4+k]);
        upk2(S2[p][k], f[16+p*8+k], f[16+p*8+4+k]);
    }
    f[32] = S0;
#pragma unroll
    for (int off = 16; off > 0; off >>= 1){
#pragma unroll
        for (int i = 0; i < 33; i++)
            f[i] += __shfl_down_sync(0xffffffffu, f[i], off);
    }
    if (c == 0){
#pragma unroll
        for (int i = 0; i < 33; i++) gp[i] = f[i];
    }
}

__device__ __forceinline__ void block_finalize(
    int it, int b, int tid, Shm* sh,
    const float* __restrict__ beta_a, const float* __restrict__ beta_u,
    float* __restrict__ out)
{
    if (tid < 160){
        const int o = tid >> 4, d = tid & 15;
        const float* buf = g_part[it & 1];
        const float* gp0 = &buf[((0*BB + b)*OO + o)*33];
        const float* gp1 = &buf[((1*BB + b)*OO + o)*33];
        const float T1 = __ldcg(gp0 + d)      + __ldcg(gp1 + d);
        const float T2 = __ldcg(gp0 + 16 + d) + __ldcg(gp1 + 16 + d);
        const float S0 = __ldcg(gp0 + 32)     + __ldcg(gp1 + 32);
        const float mu_prev = (it == 0) ? 0.f : sh->Mu[o*16 + d];

        /* exact shifted-moment identity in fp64 (cancellation-safe) */
        const double S0d = (double)S0;
        const double rsd = S0d + (double)EPSV;
        const double S1d = (double)T1 + (double)mu_prev * S0d;
        const double mud = S1d / rsd;
        const double e   = mud - (double)mu_prev;
        double varnum = (double)T2 - 2.0*e*(double)T1 + e*e*S0d;
        if (varnum < 0.0) varnum = 0.0;
        const double vard = varnum / rsd + (double)EPSV;

        const float mu   = (float)mud;
        const float var  = (float)vard;
        const float lvar = logf(var);
        const float iv   = 1.0f/var;
        const float rs   = (float)rsd;

        float r1 = lvar;
#pragma unroll
        for (int m = 8; m > 0; m >>= 1)
            r1 += __shfl_xor_sync(0xffffffffu, r1, m);

        const float cost     = rs * (16.0f*beta_u[o] + 0.5f*r1);
        const float inv_temp = 1.0f + (float)it;
        const float z        = inv_temp * (beta_a[o] - cost);
        const float actv     = 1.0f / (1.0f + expf(-z));

        if (it < 2){
            const int p = d >> 3, hi = (d >> 2) & 1, k = d & 3;
            ((float*)&sh->A2pk[o*8 + p*4 + k])[hi] = -0.5f*iv*LOG2E;
            ((float*)&sh->Mpk [o*8 + p*4 + k])[hi] = -mu;
            sh->Mu[o*16 + d] = mu;
            if (d == 0)
                sh->C0[o] = (logf(actv + EPSV) - 0.5f*(16.0f*LN2PI + r1)) * LOG2E;
        } else {
            out[(b*OO + o)*16 + d] = mu;
            if (d == 0) out[BB*OO*16 + b*OO + o] = actv;
        }
    }
    __syncthreads();
}

__global__ __launch_bounds__(320)
void fccaps_kernel(const float* __restrict__ pose,
                   const float* __restrict__ act,
                   const float* __restrict__ wmat,
                   const float* __restrict__ beta_a,
                   const float* __restrict__ beta_u,
                   float* __restrict__ out)
{
    __shared__ Shm sh;

    const int c   = threadIdx.x;
    const int o   = threadIdx.y;
    const int tid = o*32 + c;
    const int b    = blockIdx.x >> 1;
    const int half = blockIdx.x & 1;
    const int s0   = half * HALF_S;

    for (int i = tid; i < HALF_S*CC; i += 320)
        sh.act[i] = act[(size_t)b*NN + (size_t)s0*CC + i];
    if (tid < HALF_S){
        const int s = s0 + tid;
        sh.offs[tid] = pk2(((s % WW) + 0.5f)*(1.0f/WW),
                           ((s / WW) + 0.5f)*(1.0f/HH));
    }
    if (tid == 0) sh.e0 = *(volatile unsigned*)&g_epoch;

    u64 wpk[4][4];
#pragma unroll
    for (int j = 0; j < 4; j++)
#pragma unroll
    for (int k = 0; k < 4; k++){
        const float wv = wmat[((size_t)(c*OO + o))*16 + j*4 + k];
        wpk[j][k] = pk2(wv, wv);
    }
    __syncthreads();
    const unsigned e0 = sh.e0;

    const float* pose_blk = pose + ((size_t)b*NN + (size_t)s0*CC)*16;
    const size_t gpi = (((size_t)half*BB + b)*OO + o)*33;

    stats_pass<0>(pose_blk, &sh, wpk, c, o, &g_part[0][gpi]);
    grid_barrier(e0 + 1);
    block_finalize(0, b, tid, &sh, beta_a, beta_u, out);

    stats_pass<1>(pose_blk, &sh, wpk, c, o, &g_part[1][gpi]);
    grid_barrier(e0 + 2);
    block_finalize(1, b, tid, &sh, beta_a, beta_u, out);

    stats_pass<2>(pose_blk, &sh, wpk, c, o, &g_part[0][gpi]);
    grid_barrier(e0 + 3);
    if (half == 0)
        block_finalize(2, b, tid, &sh, beta_a, beta_u, out);
}

extern "C" void kernel_launch(void* const* d_in, const int* in_sizes, int n_in,
                              void* d_out, int out_size)
{
    const float* pose = (const float*)d_in[0];  // (B,H,W,C,16)
    const float* actv = (const float*)d_in[1];  // (B,H,W,C,1)
    const float* wmat = (const float*)d_in[2];  // (C,O,4,4)
    const float* ba   = (const float*)d_in[3];  // (1,1,O,1)
    const float* bu   = (const float*)d_in[4];  // (1,1,O,1)
    float* out = (float*)d_out;                 // pose(B,O,16) then act(B,O)

    dim3 blk(32, 10);
    fccaps_kernel<<<NBLK, blk>>>(pose, actv, wmat, ba, bu, out);
}

// round 7
// speedup vs baseline: 1.8840x; 1.0900x over previous
#include <cuda_runtime.h>
#include <math.h>

#define BB 64
#define HH 14
#define WW 14
#define CC 32
#define OO 10
#define NN (HH*WW*CC)          /* 6272 */
#define SPATIAL (HH*WW)        /* 196  */
#define HALF_S 98
#define NBLK 128               /* persistent blocks */
#define G 8                    /* points per staged group */
#define NGRP 13                /* 12 groups of 8 + one of 2 */
#define EPSV 1e-9f
#define LOG2E 1.4426950408889634f
#define LN2PI 1.8378770664093453f

/* double-buffered cross-block partials: [parity][half][b][o][33] */
__device__ float g_part[2][2*BB*OO*33];
__device__ unsigned int g_ctr;
__device__ unsigned int g_epoch;

typedef unsigned long long u64;
__device__ __forceinline__ u64 pk2(float lo, float hi){ u64 r; asm("mov.b64 %0,{%1,%2};" :"=l"(r):"f"(lo),"f"(hi)); return r; }
__device__ __forceinline__ void upk2(u64 a, float& lo, float& hi){ asm("mov.b64 {%0,%1},%2;":"=f"(lo),"=f"(hi):"l"(a)); }
__device__ __forceinline__ u64 fma2(u64 a,u64 b,u64 c){ u64 r; asm("fma.rn.f32x2 %0,%1,%2,%3;":"=l"(r):"l"(a),"l"(b),"l"(c)); return r; }
__device__ __forceinline__ u64 add2(u64 a,u64 b){ u64 r; asm("add.rn.f32x2 %0,%1,%2;":"=l"(r):"l"(a),"l"(b)); return r; }
__device__ __forceinline__ u64 mul2(u64 a,u64 b){ u64 r; asm("mul.rn.f32x2 %0,%1,%2;":"=l"(r):"l"(a),"l"(b)); return r; }
__device__ __forceinline__ float ex2f(float x){ float r; asm("ex2.approx.f32 %0,%1;":"=f"(r):"f"(x)); return r; }
__device__ __forceinline__ float rcpf(float x){ float r; asm("rcp.approx.f32 %0,%1;":"=f"(r):"f"(x)); return r; }

struct Shm {
    float  act [HALF_S*CC];      /* 12544 B */
    float  sbuf[G*CC*18];        /* 18432 B : pair-swizzled pose, stride 18 */
    u64    offs[HALF_S];         /* packed {w_off, h_off} */
    float  lgb [4*OO*33];        /* logit exchange, 4 points */
    float2 mrs [4*CC];           /* {max, rcp(sum)} per (point, c) */
    u64    A2pk[OO*8];           /* packed -0.5/var*log2e */
    u64    Mpk [OO*8];           /* packed -mu */
    float  Mu  [OO*16];
    float  C0  [OO];
    unsigned e0;
};

__device__ __forceinline__ void grid_barrier(unsigned target_epoch){
    __threadfence();
    __syncthreads();
    if (threadIdx.x == 0 && threadIdx.y == 0){
        unsigned a = atomicAdd(&g_ctr, 1u);
        if (a == NBLK-1u){
            atomicExch(&g_ctr, 0u);
            __threadfence();
            atomicAdd(&g_epoch, 1u);
        } else {
            while ((int)(*(volatile unsigned*)&g_epoch) - (int)target_epoch < 0) { }
        }
    }
    __syncthreads();
}

/* Process a batch of P points: sweep1 (votes->u, logits), parallel reducers,
   sweep2 (rr, accumulate). u lives in registers between sweeps. */
template<int IT, int P>
__device__ __forceinline__ void process_batch(
    Shm* sh, int gpt0 /* point index within half (0..97) */, int lpt0 /* within group */,
    const u64 wpk[4][4], const u64 A2[2][4], const u64 nMU[2][4], float C0,
    int c, int o, float& S0, u64 S1[2][4], u64 S2[2][4])
{
    u64 u[P][2][4];
    float lg[P];

    /* ---- sweep 1: votes -> u (centered), logits ---- */
#pragma unroll
    for (int lp = 0; lp < P; lp++){
        const u64* pp8 = (const u64*)(sh->sbuf) + ((size_t)(lpt0+lp)*CC + c)*9;
        const u64 j0a = pp8[0], j1a = pp8[1], j2a = pp8[2], j3a = pp8[3];
        const u64 j0b = pp8[4], j1b = pp8[5], j2b = pp8[6], j3b = pp8[7];
#pragma unroll
        for (int k = 0; k < 4; k++){
            u64 a0, a1;
            if (IT > 0){ a0 = fma2(j0a, wpk[0][k], nMU[0][k]);
                         a1 = fma2(j0b, wpk[0][k], nMU[1][k]); }
            else       { a0 = mul2(j0a, wpk[0][k]);
                         a1 = mul2(j0b, wpk[0][k]); }
            a0 = fma2(j1a, wpk[1][k], a0);
            a1 = fma2(j1b, wpk[1][k], a1);
            a0 = fma2(j2a, wpk[2][k], a0);
            a1 = fma2(j2b, wpk[2][k], a1);
            a0 = fma2(j3a, wpk[3][k], a0);
            a1 = fma2(j3b, wpk[3][k], a1);
            u[lp][0][k] = a0; u[lp][1][k] = a1;
        }
        u[lp][0][3] = add2(u[lp][0][3], sh->offs[gpt0+lp]);

        if (IT > 0){
            u64 q, l2;
            q = mul2(u[lp][0][0], u[lp][0][0]); l2 = mul2(q, A2[0][0]);
            q = mul2(u[lp][0][1], u[lp][0][1]); l2 = fma2(q, A2[0][1], l2);
            q = mul2(u[lp][0][2], u[lp][0][2]); l2 = fma2(q, A2[0][2], l2);
            q = mul2(u[lp][0][3], u[lp][0][3]); l2 = fma2(q, A2[0][3], l2);
            q = mul2(u[lp][1][0], u[lp][1][0]); l2 = fma2(q, A2[1][0], l2);
            q = mul2(u[lp][1][1], u[lp][1][1]); l2 = fma2(q, A2[1][1], l2);
            q = mul2(u[lp][1][2], u[lp][1][2]); l2 = fma2(q, A2[1][2], l2);
            q = mul2(u[lp][1][3], u[lp][1][3]); l2 = fma2(q, A2[1][3], l2);
            float x, y; upk2(l2, x, y);
            lg[lp] = C0 + (x + y);
            sh->lgb[lp*(OO*33) + o*33 + c] = lg[lp];
        }
    }

    /* ---- parallel reducers: warp o reduces point o ---- */
    if (IT > 0){
        __syncthreads();
        if (o < P){
            const float* lb = sh->lgb + o*(OO*33) + c;
            float lv[OO];
#pragma unroll
            for (int oo = 0; oo < OO; oo++) lv[oo] = lb[oo*33];
            float m = lv[0];
#pragma unroll
            for (int oo = 1; oo < OO; oo++) m = fmaxf(m, lv[oo]);
            float s = 0.f;
#pragma unroll
            for (int oo = 0; oo < OO; oo++) s += ex2f(lv[oo] - m);
            sh->mrs[o*CC + c] = make_float2(m, rcpf(s));
        }
        __syncthreads();
    }

    /* ---- sweep 2: rr, accumulate ---- */
#pragma unroll
    for (int lp = 0; lp < P; lp++){
        float rr;
        if (IT == 0){
            rr = 0.1f;
        } else {
            const float2 mr = sh->mrs[lp*CC + c];
            rr = ex2f(lg[lp] - mr.x) * mr.y;
        }
        const float rp = rr * sh->act[(gpt0+lp)*CC + c];
        S0 += rp;
        const u64 rk = pk2(rp, rp);
#pragma unroll
        for (int p = 0; p < 2; p++)
#pragma unroll
        for (int k = 0; k < 4; k++){
            const u64 ru = mul2(rk, u[lp][p][k]);
            S1[p][k] = add2(S1[p][k], ru);
            S2[p][k] = fma2(ru, u[lp][p][k], S2[p][k]);
        }
    }
}

template<int IT>
__device__ __forceinline__ void stats_pass(
    const float* __restrict__ pose_blk, Shm* sh,
    const u64 wpk[4][4], int c, int o, float* gp)
{
    u64 A2[2][4], nMU[2][4]; float C0 = 0.f;
    if (IT > 0){
        C0 = sh->C0[o];
#pragma unroll
        for (int p = 0; p < 2; p++)
#pragma unroll
        for (int k = 0; k < 4; k++){
            A2[p][k]  = sh->A2pk[o*8 + p*4 + k];
            nMU[p][k] = sh->Mpk [o*8 + p*4 + k];
        }
    }

    u64 S1[2][4], S2[2][4]; float S0 = 0.f;
#pragma unroll
    for (int p = 0; p < 2; p++)
#pragma unroll
    for (int k = 0; k < 4; k++){ S1[p][k] = 0ull; S2[p][k] = 0ull; }

    const int t = o*32 + c;
    const float4* pb4 = (const float4*)pose_blk;

    /* prologue: prefetch group 0 (256 rows) */
    float4 pr0, pr1, pr2, pr3;
    if (t < G*CC){
        const float4* s = pb4 + (size_t)t*4;
        pr0 = s[0]; pr1 = s[1]; pr2 = s[2]; pr3 = s[3];
    }

    for (int g = 0; g < NGRP; g++){
        const int pts  = (g == NGRP-1) ? (HALF_S - (NGRP-1)*G) : G;   /* 8 or 2 */
        if (t < pts*CC){
            float2* sb2 = (float2*)&sh->sbuf[t*18];
            sb2[0] = make_float2(pr0.x, pr1.x);
            sb2[1] = make_float2(pr0.y, pr1.y);
            sb2[2] = make_float2(pr0.z, pr1.z);
            sb2[3] = make_float2(pr0.w, pr1.w);
            sb2[4] = make_float2(pr2.x, pr3.x);
            sb2[5] = make_float2(pr2.y, pr3.y);
            sb2[6] = make_float2(pr2.z, pr3.z);
            sb2[7] = make_float2(pr2.w, pr3.w);
        }
        __syncthreads();
        if (g < NGRP-1){
            const int npts = (g == NGRP-2) ? (HALF_S - (NGRP-1)*G) : G;
            if (t < npts*CC){
                const float4* s = pb4 + ((size_t)(g+1)*G*CC + t)*4;
                pr0 = s[0]; pr1 = s[1]; pr2 = s[2]; pr3 = s[3];
            }
        }

        if (pts == G){
            process_batch<IT,4>(sh, g*G,     0, wpk, A2, nMU, C0, c, o, S0, S1, S2);
            process_batch<IT,4>(sh, g*G + 4, 4, wpk, A2, nMU, C0, c, o, S0, S1, S2);
        } else {
            process_batch<IT,2>(sh, g*G,     0, wpk, A2, nMU, C0, c, o, S0, S1, S2);
        }
        if (IT == 0) __syncthreads();   /* order sbuf reads before next STS */
    }

    /* unpack to true-d order, warp-reduce over c, lane0 writes partials */
    float f[33];
#pragma unroll
    for (int p = 0; p < 2; p++)
#pragma unroll
    for (int k = 0; k < 4; k++){
        upk2(S1[p][k], f[p*8+k],    f[p*8+4+k]);
        upk2(S2[p][k], f[16+p*8+k], f[16+p*8+4+k]);
    }
    f[32] = S0;
#pragma unroll
    for (int off = 16; off > 0; off >>= 1){
#pragma unroll
        for (int i = 0; i < 33; i++)
            f[i] += __shfl_down_sync(0xffffffffu, f[i], off);
    }
    if (c == 0){
#pragma unroll
        for (int i = 0; i < 33; i++) gp[i] = f[i];
    }
}

__device__ __forceinline__ void block_finalize(
    int it, int b, int tid, Shm* sh,
    const float* __restrict__ beta_a, const float* __restrict__ beta_u,
    float* __restrict__ out)
{
    if (tid < 160){
        const int o = tid >> 4, d = tid & 15;
        const float* buf = g_part[it & 1];
        const float* gp0 = &buf[((0*BB + b)*OO + o)*33];
        const float* gp1 = &buf[((1*BB + b)*OO + o)*33];
        const float T1 = __ldcg(gp0 + d)      + __ldcg(gp1 + d);
        const float T2 = __ldcg(gp0 + 16 + d) + __ldcg(gp1 + 16 + d);
        const float S0 = __ldcg(gp0 + 32)     + __ldcg(gp1 + 32);
        const float mu_prev = (it == 0) ? 0.f : sh->Mu[o*16 + d];

        /* exact shifted-moment identity in fp64 (cancellation-safe) */
        const double S0d = (double)S0;
        const double rsd = S0d + (double)EPSV;
        const double S1d = (double)T1 + (double)mu_prev * S0d;
        const double mud = S1d / rsd;
        const double e   = mud - (double)mu_prev;
        double varnum = (double)T2 - 2.0*e*(double)T1 + e*e*S0d;
        if (varnum < 0.0) varnum = 0.0;
        const double vard = varnum / rsd + (double)EPSV;

        const float mu   = (float)mud;
        const float var  = (float)vard;
        const float lvar = logf(var);
        const float iv   = 1.0f/var;
        const float rs   = (float)rsd;

        float r1 = lvar;
#pragma unroll
        for (int m = 8; m > 0; m >>= 1)
            r1 += __shfl_xor_sync(0xffffffffu, r1, m);

        const float cost     = rs * (16.0f*beta_u[o] + 0.5f*r1);
        const float inv_temp = 1.0f + (float)it;
        const float z        = inv_temp * (beta_a[o] - cost);
        const float actv     = 1.0f / (1.0f + expf(-z));

        if (it < 2){
            const int p = d >> 3, hi = (d >> 2) & 1, k = d & 3;
            ((float*)&sh->A2pk[o*8 + p*4 + k])[hi] = -0.5f*iv*LOG2E;
            ((float*)&sh->Mpk [o*8 + p*4 + k])[hi] = -mu;
            sh->Mu[o*16 + d] = mu;
            if (d == 0)
                sh->C0[o] = (logf(actv + EPSV) - 0.5f*(16.0f*LN2PI + r1)) * LOG2E;
        } else {
            out[(b*OO + o)*16 + d] = mu;
            if (d == 0) out[BB*OO*16 + b*OO + o] = actv;
        }
    }
    __syncthreads();
}

__global__ __launch_bounds__(320)
void fccaps_kernel(const float* __restrict__ pose,
                   const float* __restrict__ act,
                   const float* __restrict__ wmat,
                   const float* __restrict__ beta_a,
                   const float* __restrict__ beta_u,
                   float* __restrict__ out)
{
    __shared__ Shm sh;

    const int c   = threadIdx.x;
    const int o   = threadIdx.y;
    const int tid = o*32 + c;
    const int b    = blockIdx.x >> 1;
    const int half = blockIdx.x & 1;
    const int s0   = half * HALF_S;

    for (int i = tid; i < HALF_S*CC; i += 320)
        sh.act[i] = act[(size_t)b*NN + (size_t)s0*CC + i];
    if (tid < HALF_S){
        const int s = s0 + tid;
        sh.offs[tid] = pk2(((s % WW) + 0.5f)*(1.0f/WW),
                           ((s / WW) + 0.5f)*(1.0f/HH));
    }
    if (tid == 0) sh.e0 = *(volatile unsigned*)&g_epoch;

    u64 wpk[4][4];
#pragma unroll
    for (int j = 0; j < 4; j++)
#pragma unroll
    for (int k = 0; k < 4; k++){
        const float wv = wmat[((size_t)(c*OO + o))*16 + j*4 + k];
        wpk[j][k] = pk2(wv, wv);
    }
    __syncthreads();
    const unsigned e0 = sh.e0;

    const float* pose_blk = pose + ((size_t)b*NN + (size_t)s0*CC)*16;
    const size_t gpi = (((size_t)half*BB + b)*OO + o)*33;

    stats_pass<0>(pose_blk, &sh, wpk, c, o, &g_part[0][gpi]);
    grid_barrier(e0 + 1);
    block_finalize(0, b, tid, &sh, beta_a, beta_u, out);

    stats_pass<1>(pose_blk, &sh, wpk, c, o, &g_part[1][gpi]);
    grid_barrier(e0 + 2);
    block_finalize(1, b, tid, &sh, beta_a, beta_u, out);

    stats_pass<2>(pose_blk, &sh, wpk, c, o, &g_part[0][gpi]);
    grid_barrier(e0 + 3);
    if (half == 0)
        block_finalize(2, b, tid, &sh, beta_a, beta_u, out);
}

extern "C" void kernel_launch(void* const* d_in, const int* in_sizes, int n_in,
                              void* d_out, int out_size)
{
    const float* pose = (const float*)d_in[0];  // (B,H,W,C,16)
    const float* actv = (const float*)d_in[1];  // (B,H,W,C,1)
    const float* wmat = (const float*)d_in[2];  // (C,O,4,4)
    const float* ba   = (const float*)d_in[3];  // (1,1,O,1)
    const float* bu   = (const float*)d_in[4];  // (1,1,O,1)
    float* out = (float*)d_out;                 // pose(B,O,16) then act(B,O)

    dim3 blk(32, 10);
    fccaps_kernel<<<NBLK, blk>>>(pose, actv, wmat, ba, bu, out);
}

// round 8
// speedup vs baseline: 1.8965x; 1.0066x over previous
#include <cuda_runtime.h>
#include <math.h>

#define BB 64
#define HH 14
#define WW 14
#define CC 32
#define OO 10
#define NN (HH*WW*CC)          /* 6272 */
#define SPATIAL (HH*WW)        /* 196  */
#define HALF_S 98
#define NBLK 128               /* persistent blocks */
#define G 8                    /* points per staged group */
#define NGRP 13                /* 12 groups of 8 + one of 2 */
#define EPSV 1e-9f
#define LOG2E 1.4426950408889634f
#define LN2PI 1.8378770664093453f

/* double-buffered cross-block partials: [parity][half][b][o][33] */
__device__ float g_part[2][2*BB*OO*33];
__device__ unsigned int g_ctr;
__device__ unsigned int g_epoch;

typedef unsigned long long u64;
__device__ __forceinline__ u64 pk2(float lo, float hi){ u64 r; asm("mov.b64 %0,{%1,%2};" :"=l"(r):"f"(lo),"f"(hi)); return r; }
__device__ __forceinline__ void upk2(u64 a, float& lo, float& hi){ asm("mov.b64 {%0,%1},%2;":"=f"(lo),"=f"(hi):"l"(a)); }
__device__ __forceinline__ u64 fma2(u64 a,u64 b,u64 c){ u64 r; asm("fma.rn.f32x2 %0,%1,%2,%3;":"=l"(r):"l"(a),"l"(b),"l"(c)); return r; }
__device__ __forceinline__ u64 add2(u64 a,u64 b){ u64 r; asm("add.rn.f32x2 %0,%1,%2;":"=l"(r):"l"(a),"l"(b)); return r; }
__device__ __forceinline__ u64 mul2(u64 a,u64 b){ u64 r; asm("mul.rn.f32x2 %0,%1,%2;":"=l"(r):"l"(a),"l"(b)); return r; }
__device__ __forceinline__ float ex2f(float x){ float r; asm("ex2.approx.f32 %0,%1;":"=f"(r):"f"(x)); return r; }
__device__ __forceinline__ float rcpf(float x){ float r; asm("rcp.approx.f32 %0,%1;":"=f"(r):"f"(x)); return r; }

struct Shm {
    float  act [HALF_S*CC];      /* 12544 B */
    float  sbuf[G*CC*18];        /* 18432 B : pair-swizzled pose, stride 18 */
    u64    offs[HALF_S];         /* packed {w_off, h_off} */
    float  lgb [4*OO*33];        /* logit exchange, 4 points */
    float2 mrs [4*CC];           /* {max, rcp(sum)} per (point, c) */
    u64    A2pk[OO*8];           /* packed -0.5/var*log2e */
    u64    Mpk [OO*8];           /* packed -mu */
    float  Mu  [OO*16];
    float  C0  [OO];
    unsigned e0;
};

__device__ __forceinline__ void grid_barrier(unsigned target_epoch){
    __threadfence();
    __syncthreads();
    if (threadIdx.x == 0 && threadIdx.y == 0){
        unsigned a = atomicAdd(&g_ctr, 1u);
        if (a == NBLK-1u){
            atomicExch(&g_ctr, 0u);
            __threadfence();
            atomicAdd(&g_epoch, 1u);
        } else {
            while ((int)(*(volatile unsigned*)&g_epoch) - (int)target_epoch < 0) { }
        }
    }
    __syncthreads();
}

/* Process a batch of P points: sweep1 (votes->u, logits) with pose loads
   software-pipelined one point ahead, parallel reducers (tree max/sum),
   sweep2 (rr, accumulate). u lives in registers between sweeps. */
template<int IT, int P>
__device__ __forceinline__ void process_batch(
    Shm* sh, int gpt0 /* point index within half (0..97) */, int lpt0 /* within group */,
    const u64 wpk[4][4], const u64 A2[2][4], const u64 nMU[2][4], float C0,
    int c, int o, float& S0, u64 S1[2][4], u64 S2[2][4])
{
    u64 u[P][2][4];
    float lg[P];
    u64 pp[2][8];                 /* double-buffered pose, 8 u64 per point */

    /* preload point 0's pose */
    {
        const u64* s = (const u64*)(sh->sbuf) + ((size_t)lpt0*CC + c)*9;
#pragma unroll
        for (int i = 0; i < 8; i++) pp[0][i] = s[i];
    }

    /* ---- sweep 1: votes -> u (centered), logits ---- */
#pragma unroll
    for (int lp = 0; lp < P; lp++){
        /* prefetch next point's pose under this point's FFMA block */
        if (lp + 1 < P){
            const u64* s = (const u64*)(sh->sbuf) + ((size_t)(lpt0+lp+1)*CC + c)*9;
#pragma unroll
            for (int i = 0; i < 8; i++) pp[(lp+1)&1][i] = s[i];
        }
        const u64* q = pp[lp&1];
        const u64 j0a = q[0], j1a = q[1], j2a = q[2], j3a = q[3];
        const u64 j0b = q[4], j1b = q[5], j2b = q[6], j3b = q[7];
#pragma unroll
        for (int k = 0; k < 4; k++){
            u64 a0, a1;
            if (IT > 0){ a0 = fma2(j0a, wpk[0][k], nMU[0][k]);
                         a1 = fma2(j0b, wpk[0][k], nMU[1][k]); }
            else       { a0 = mul2(j0a, wpk[0][k]);
                         a1 = mul2(j0b, wpk[0][k]); }
            a0 = fma2(j1a, wpk[1][k], a0);
            a1 = fma2(j1b, wpk[1][k], a1);
            a0 = fma2(j2a, wpk[2][k], a0);
            a1 = fma2(j2b, wpk[2][k], a1);
            a0 = fma2(j3a, wpk[3][k], a0);
            a1 = fma2(j3b, wpk[3][k], a1);
            u[lp][0][k] = a0; u[lp][1][k] = a1;
        }
        u[lp][0][3] = add2(u[lp][0][3], sh->offs[gpt0+lp]);

        if (IT > 0){
            u64 q2, l2;
            q2 = mul2(u[lp][0][0], u[lp][0][0]); l2 = mul2(q2, A2[0][0]);
            q2 = mul2(u[lp][0][1], u[lp][0][1]); l2 = fma2(q2, A2[0][1], l2);
            q2 = mul2(u[lp][0][2], u[lp][0][2]); l2 = fma2(q2, A2[0][2], l2);
            q2 = mul2(u[lp][0][3], u[lp][0][3]); l2 = fma2(q2, A2[0][3], l2);
            q2 = mul2(u[lp][1][0], u[lp][1][0]); l2 = fma2(q2, A2[1][0], l2);
            q2 = mul2(u[lp][1][1], u[lp][1][1]); l2 = fma2(q2, A2[1][1], l2);
            q2 = mul2(u[lp][1][2], u[lp][1][2]); l2 = fma2(q2, A2[1][2], l2);
            q2 = mul2(u[lp][1][3], u[lp][1][3]); l2 = fma2(q2, A2[1][3], l2);
            float x, y; upk2(l2, x, y);
            lg[lp] = C0 + (x + y);
            sh->lgb[lp*(OO*33) + o*33 + c] = lg[lp];
        }
    }

    /* ---- parallel reducers: warp o reduces point o (tree max/sum) ---- */
    if (IT > 0){
        __syncthreads();
        if (o < P){
            const float* lb = sh->lgb + o*(OO*33) + c;
            float lv[OO];
#pragma unroll
            for (int oo = 0; oo < OO; oo++) lv[oo] = lb[oo*33];
            /* depth-4 max tree */
            const float m01 = fmaxf(lv[0], lv[1]);
            const float m23 = fmaxf(lv[2], lv[3]);
            const float m45 = fmaxf(lv[4], lv[5]);
            const float m67 = fmaxf(lv[6], lv[7]);
            const float m89 = fmaxf(lv[8], lv[9]);
            const float m   = fmaxf(fmaxf(fmaxf(m01, m23), fmaxf(m45, m67)), m89);
            float e0 = ex2f(lv[0]-m), e1 = ex2f(lv[1]-m);
            float e2 = ex2f(lv[2]-m), e3 = ex2f(lv[3]-m);
            float e4 = ex2f(lv[4]-m), e5 = ex2f(lv[5]-m);
            float e6 = ex2f(lv[6]-m), e7 = ex2f(lv[7]-m);
            float e8 = ex2f(lv[8]-m), e9 = ex2f(lv[9]-m);
            const float s = (((e0+e1)+(e2+e3)) + ((e4+e5)+(e6+e7))) + (e8+e9);
            sh->mrs[o*CC + c] = make_float2(m, rcpf(s));
        }
        __syncthreads();
    }

    /* ---- sweep 2: rr, accumulate (loads hoisted ahead of ex2) ---- */
    float2 mr[P]; float av[P];
#pragma unroll
    for (int lp = 0; lp < P; lp++){
        if (IT > 0) mr[lp] = sh->mrs[lp*CC + c];
        av[lp] = sh->act[(gpt0+lp)*CC + c];
    }
#pragma unroll
    for (int lp = 0; lp < P; lp++){
        float rr;
        if (IT == 0) rr = 0.1f;
        else         rr = ex2f(lg[lp] - mr[lp].x) * mr[lp].y;
        const float rp = rr * av[lp];
        S0 += rp;
        const u64 rk = pk2(rp, rp);
#pragma unroll
        for (int p = 0; p < 2; p++)
#pragma unroll
        for (int k = 0; k < 4; k++){
            const u64 ru = mul2(rk, u[lp][p][k]);
            S1[p][k] = add2(S1[p][k], ru);
            S2[p][k] = fma2(ru, u[lp][p][k], S2[p][k]);
        }
    }
}

template<int IT>
__device__ __forceinline__ void stats_pass(
    const float* __restrict__ pose_blk, Shm* sh,
    const u64 wpk[4][4], int c, int o, float* gp)
{
    u64 A2[2][4], nMU[2][4]; float C0 = 0.f;
    if (IT > 0){
        C0 = sh->C0[o];
#pragma unroll
        for (int p = 0; p < 2; p++)
#pragma unroll
        for (int k = 0; k < 4; k++){
            A2[p][k]  = sh->A2pk[o*8 + p*4 + k];
            nMU[p][k] = sh->Mpk [o*8 + p*4 + k];
        }
    }

    u64 S1[2][4], S2[2][4]; float S0 = 0.f;
#pragma unroll
    for (int p = 0; p < 2; p++)
#pragma unroll
    for (int k = 0; k < 4; k++){ S1[p][k] = 0ull; S2[p][k] = 0ull; }

    const int t = o*32 + c;
    const float4* pb4 = (const float4*)pose_blk;

    /* prologue: prefetch group 0 (256 rows) */
    float4 pr0, pr1, pr2, pr3;
    if (t < G*CC){
        const float4* s = pb4 + (size_t)t*4;
        pr0 = s[0]; pr1 = s[1]; pr2 = s[2]; pr3 = s[3];
    }

    for (int g = 0; g < NGRP; g++){
        const int pts  = (g == NGRP-1) ? (HALF_S - (NGRP-1)*G) : G;   /* 8 or 2 */
        if (t < pts*CC){
            float2* sb2 = (float2*)&sh->sbuf[t*18];
            sb2[0] = make_float2(pr0.x, pr1.x);
            sb2[1] = make_float2(pr0.y, pr1.y);
            sb2[2] = make_float2(pr0.z, pr1.z);
            sb2[3] = make_float2(pr0.w, pr1.w);
            sb2[4] = make_float2(pr2.x, pr3.x);
            sb2[5] = make_float2(pr2.y, pr3.y);
            sb2[6] = make_float2(pr2.z, pr3.z);
            sb2[7] = make_float2(pr2.w, pr3.w);
        }
        __syncthreads();
        if (g < NGRP-1){
            const int npts = (g == NGRP-2) ? (HALF_S - (NGRP-1)*G) : G;
            if (t < npts*CC){
                const float4* s = pb4 + ((size_t)(g+1)*G*CC + t)*4;
                pr0 = s[0]; pr1 = s[1]; pr2 = s[2]; pr3 = s[3];
            }
        }

        if (pts == G){
            process_batch<IT,4>(sh, g*G,     0, wpk, A2, nMU, C0, c, o, S0, S1, S2);
            process_batch<IT,4>(sh, g*G + 4, 4, wpk, A2, nMU, C0, c, o, S0, S1, S2);
        } else {
            process_batch<IT,2>(sh, g*G,     0, wpk, A2, nMU, C0, c, o, S0, S1, S2);
        }
        if (IT == 0) __syncthreads();   /* order sbuf reads before next STS */
    }

    /* unpack to true-d order, warp-reduce over c, lane0 writes partials */
    float f[33];
#pragma unroll
    for (int p = 0; p < 2; p++)
#pragma unroll
    for (int k = 0; k < 4; k++){
        upk2(S1[p][k], f[p*8+k],    f[p*8+4+k]);
        upk2(S2[p][k], f[16+p*8+k], f[16+p*8+4+k]);
    }
    f[32] = S0;
#pragma unroll
    for (int off = 16; off > 0; off >>= 1){
#pragma unroll
        for (int i = 0; i < 33; i++)
            f[i] += __shfl_down_sync(0xffffffffu, f[i], off);
    }
    if (c == 0){
#pragma unroll
        for (int i = 0; i < 33; i++) gp[i] = f[i];
    }
}

__device__ __forceinline__ void block_finalize(
    int it, int b, int tid, Shm* sh,
    const float* __restrict__ beta_a, const float* __restrict__ beta_u,
    float* __restrict__ out)
{
    if (tid < 160){
        const int o = tid >> 4, d = tid & 15;
        const float* buf = g_part[it & 1];
        const float* gp0 = &buf[((0*BB + b)*OO + o)*33];
        const float* gp1 = &buf[((1*BB + b)*OO + o)*33];
        const float T1 = __ldcg(gp0 + d)      + __ldcg(gp1 + d);
        const float T2 = __ldcg(gp0 + 16 + d) + __ldcg(gp1 + 16 + d);
        const float S0 = __ldcg(gp0 + 32)     + __ldcg(gp1 + 32);
        const float mu_prev = (it == 0) ? 0.f : sh->Mu[o*16 + d];

        /* exact shifted-moment identity in fp64 (cancellation-safe) */
        const double S0d = (double)S0;
        const double rsd = S0d + (double)EPSV;
        const double S1d = (double)T1 + (double)mu_prev * S0d;
        const double mud = S1d / rsd;
        const double e   = mud - (double)mu_prev;
        double varnum = (double)T2 - 2.0*e*(double)T1 + e*e*S0d;
        if (varnum < 0.0) varnum = 0.0;
        const double vard = varnum / rsd + (double)EPSV;

        const float mu   = (float)mud;
        const float var  = (float)vard;
        const float lvar = logf(var);
        const float iv   = 1.0f/var;
        const float rs   = (float)rsd;

        float r1 = lvar;
#pragma unroll
        for (int m = 8; m > 0; m >>= 1)
            r1 += __shfl_xor_sync(0xffffffffu, r1, m);

        const float cost     = rs * (16.0f*beta_u[o] + 0.5f*r1);
        const float inv_temp = 1.0f + (float)it;
        const float z        = inv_temp * (beta_a[o] - cost);
        const float actv     = 1.0f / (1.0f + expf(-z));

        if (it < 2){
            const int p = d >> 3, hi = (d >> 2) & 1, k = d & 3;
            ((float*)&sh->A2pk[o*8 + p*4 + k])[hi] = -0.5f*iv*LOG2E;
            ((float*)&sh->Mpk [o*8 + p*4 + k])[hi] = -mu;
            sh->Mu[o*16 + d] = mu;
            if (d == 0)
                sh->C0[o] = (logf(actv + EPSV) - 0.5f*(16.0f*LN2PI + r1)) * LOG2E;
        } else {
            out[(b*OO + o)*16 + d] = mu;
            if (d == 0) out[BB*OO*16 + b*OO + o] = actv;
        }
    }
    __syncthreads();
}

__global__ __launch_bounds__(320)
void fccaps_kernel(const float* __restrict__ pose,
                   const float* __restrict__ act,
                   const float* __restrict__ wmat,
                   const float* __restrict__ beta_a,
                   const float* __restrict__ beta_u,
                   float* __restrict__ out)
{
    __shared__ Shm sh;

    const int c   = threadIdx.x;
    const int o   = threadIdx.y;
    const int tid = o*32 + c;
    const int b    = blockIdx.x >> 1;
    const int half = blockIdx.x & 1;
    const int s0   = half * HALF_S;

    for (int i = tid; i < HALF_S*CC; i += 320)
        sh.act[i] = act[(size_t)b*NN + (size_t)s0*CC + i];
    if (tid < HALF_S){
        const int s = s0 + tid;
        sh.offs[tid] = pk2(((s % WW) + 0.5f)*(1.0f/WW),
                           ((s / WW) + 0.5f)*(1.0f/HH));
    }
    if (tid == 0) sh.e0 = *(volatile unsigned*)&g_epoch;

    u64 wpk[4][4];
#pragma unroll
    for (int j = 0; j < 4; j++)
#pragma unroll
    for (int k = 0; k < 4; k++){
        const float wv = wmat[((size_t)(c*OO + o))*16 + j*4 + k];
        wpk[j][k] = pk2(wv, wv);
    }
    __syncthreads();
    const unsigned e0 = sh.e0;

    const float* pose_blk = pose + ((size_t)b*NN + (size_t)s0*CC)*16;
    const size_t gpi = (((size_t)half*BB + b)*OO + o)*33;

    stats_pass<0>(pose_blk, &sh, wpk, c, o, &g_part[0][gpi]);
    grid_barrier(e0 + 1);
    block_finalize(0, b, tid, &sh, beta_a, beta_u, out);

    stats_pass<1>(pose_blk, &sh, wpk, c, o, &g_part[1][gpi]);
    grid_barrier(e0 + 2);
    block_finalize(1, b, tid, &sh, beta_a, beta_u, out);

    stats_pass<2>(pose_blk, &sh, wpk, c, o, &g_part[0][gpi]);
    grid_barrier(e0 + 3);
    if (half == 0)
        block_finalize(2, b, tid, &sh, beta_a, beta_u, out);
}

extern "C" void kernel_launch(void* const* d_in, const int* in_sizes, int n_in,
                              void* d_out, int out_size)
{
    const float* pose = (const float*)d_in[0];  // (B,H,W,C,16)
    const float* actv = (const float*)d_in[1];  // (B,H,W,C,1)
    const float* wmat = (const float*)d_in[2];  // (C,O,4,4)
    const float* ba   = (const float*)d_in[3];  // (1,1,O,1)
    const float* bu   = (const float*)d_in[4];  // (1,1,O,1)
    float* out = (float*)d_out;                 // pose(B,O,16) then act(B,O)

    dim3 blk(32, 10);
    fccaps_kernel<<<NBLK, blk>>>(pose, actv, wmat, ba, bu, out);
}